// round 6
// baseline (speedup 1.0000x reference)
#include <cuda_runtime.h>
#include <cstdint>
#include <cstddef>

#define NMAX 100000
#define EMAX 3200000
#define NBLK_SCAN ((NMAX + 1023) / 1024)

// ---------------- static device scratch (no allocation anywhere) -------------
__device__ __align__(128) float g_h1[(size_t)NMAX * 256];   // relu(x@W1+b1)
__device__ __align__(128) float g_h [(size_t)NMAX * 64];    // MLP output
__device__ __align__(128) float g_bufA[(size_t)NMAX * 64];
__device__ __align__(128) float g_bufB[(size_t)NMAX * 64];
__device__ __align__(128) float g_W1t[256 * 512];           // W1^T [256][512]
__device__ __align__(128) float g_W2t[64 * 256];            // W2^T [64][256]
__device__ __align__(128) float g_dis[NMAX];
__device__ __align__(128) int   g_cnt[NMAX];
__device__ __align__(128) int   g_incl[NMAX];
__device__ __align__(128) int   g_bsum[NBLK_SCAN + 1];
__device__ __align__(128) int   g_rowptr[NMAX + 1];
__device__ __align__(128) int   g_cursor[NMAX];
__device__ __align__(128) int   g_col[EMAX];
__device__ __align__(128) float g_w[EMAX];
__device__ int g_is64;

__device__ __forceinline__ float* bufsel(int i) {
    return i == 0 ? g_h : (i == 1 ? g_bufA : g_bufB);
}

// ---------------- dtype detection --------------------------------------------
__global__ void k_detect(const void* ei, int E, int N) {
    __shared__ int bad;
    if (threadIdx.x == 0) bad = 0;
    __syncthreads();
    const long long* p = (const long long*)ei;
    int lim = (E < 4096) ? E : 4096;
    for (int i = threadIdx.x; i < lim; i += blockDim.x) {
        long long v = p[i];
        if (v < 0 || v >= (long long)N) bad = 1;
    }
    __syncthreads();
    if (threadIdx.x == 0) g_is64 = bad ? 0 : 1;
}

__device__ __forceinline__ int edge_at(const void* ei, size_t j, int N) {
    long long v;
    if (g_is64) v = ((const long long*)ei)[j];
    else        v = (long long)((const int*)ei)[j];
    if (v < 0) v = 0;
    if (v >= N) v = N - 1;
    return (int)v;
}

// ---------------- transpose: dst[c][r] = src[r][c] ---------------------------
__global__ void k_transpose(const float* __restrict__ src, float* __restrict__ dst,
                            int R, int C) {
    __shared__ float t[32][33];
    int c0 = blockIdx.x * 32, r0 = blockIdx.y * 32;
    int x = threadIdx.x, y0 = threadIdx.y;
    #pragma unroll
    for (int dy = 0; dy < 32; dy += 8) {
        int r = r0 + y0 + dy, c = c0 + x;
        t[y0 + dy][x] = (r < R && c < C) ? src[(size_t)r * C + c] : 0.f;
    }
    __syncthreads();
    #pragma unroll
    for (int dy = 0; dy < 32; dy += 8) {
        int c = c0 + y0 + dy, r = r0 + x;
        if (c < C && r < R) dst[(size_t)c * R + r] = t[x][y0 + dy];
    }
}

// ---------------- tf32 mma.sync GEMM -----------------------------------------
// C[M x Ncols] = A[M x KTOT] @ Bt[Ncols x KTOT]^T  (+bias, optional relu)
// Block 128x64, BK=32, 8 warps as 2(M) x 4(N); warp tile 64x16 = 4x2 m16n8k8.
__device__ __forceinline__ uint32_t f2tf(float f) {
    uint32_t r;
    asm("cvt.rna.tf32.f32 %0, %1;" : "=r"(r) : "f"(f));
    return r;
}

template<int KTOT, int SEL>
__global__ void __launch_bounds__(256) mma_gemm(const float* __restrict__ Ain,
                                                const float* __restrict__ Bt,
                                                const float* __restrict__ bias,
                                                int M, int Ncols) {
    constexpr int SA = 36;                  // smem row stride (floats)
    __shared__ uint32_t As[128 * SA];
    __shared__ uint32_t Bs[64 * SA];

    const float* A = (SEL == 0) ? Ain : (const float*)g_h1;
    float* C       = (SEL == 0) ? g_h1 : g_h;

    const int tid = threadIdx.x;
    const int wid = tid >> 5;
    const int lane = tid & 31;
    const int g = lane >> 2;                // group id 0..7
    const int t = lane & 3;                 // thread-in-group 0..3
    const int row0 = blockIdx.y * 128;
    const int col0 = blockIdx.x * 64;
    const int warpM = (wid & 1) * 64;
    const int warpN = (wid >> 1) * 16;

    float acc[4][2][4];
    #pragma unroll
    for (int mt = 0; mt < 4; mt++)
        #pragma unroll
        for (int nt = 0; nt < 2; nt++)
            #pragma unroll
            for (int r = 0; r < 4; r++) acc[mt][nt][r] = 0.f;

    for (int kt = 0; kt < KTOT / 32; kt++) {
        // A tile: 128 rows x 32 k -> 1024 float4, 4 per thread (coalesced)
        #pragma unroll
        for (int i = 0; i < 4; i++) {
            int idx = tid + i * 256;
            int m = idx >> 3, k4 = idx & 7;
            int gr = row0 + m;
            float4 v = make_float4(0.f, 0.f, 0.f, 0.f);
            if (gr < M)
                v = *reinterpret_cast<const float4*>(A + (size_t)gr * KTOT + kt * 32 + k4 * 4);
            uint4 w4 = make_uint4(f2tf(v.x), f2tf(v.y), f2tf(v.z), f2tf(v.w));
            *reinterpret_cast<uint4*>(&As[m * SA + k4 * 4]) = w4;
        }
        // B tile: 64 rows x 32 k -> 512 float4, 2 per thread
        #pragma unroll
        for (int i = 0; i < 2; i++) {
            int idx = tid + i * 256;
            int n = idx >> 3, k4 = idx & 7;
            float4 v = *reinterpret_cast<const float4*>(Bt + (size_t)(col0 + n) * KTOT + kt * 32 + k4 * 4);
            uint4 w4 = make_uint4(f2tf(v.x), f2tf(v.y), f2tf(v.z), f2tf(v.w));
            *reinterpret_cast<uint4*>(&Bs[n * SA + k4 * 4]) = w4;
        }
        __syncthreads();

        #pragma unroll
        for (int kk = 0; kk < 32; kk += 8) {
            uint32_t a[4][4], b[2][2];
            #pragma unroll
            for (int mt = 0; mt < 4; mt++) {
                int mr = warpM + mt * 16 + g;
                a[mt][0] = As[mr * SA + kk + t];
                a[mt][1] = As[(mr + 8) * SA + kk + t];
                a[mt][2] = As[mr * SA + kk + t + 4];
                a[mt][3] = As[(mr + 8) * SA + kk + t + 4];
            }
            #pragma unroll
            for (int nt = 0; nt < 2; nt++) {
                int nc = warpN + nt * 8 + g;
                b[nt][0] = Bs[nc * SA + kk + t];
                b[nt][1] = Bs[nc * SA + kk + t + 4];
            }
            #pragma unroll
            for (int mt = 0; mt < 4; mt++)
                #pragma unroll
                for (int nt = 0; nt < 2; nt++)
                    asm volatile(
                        "mma.sync.aligned.m16n8k8.row.col.f32.tf32.tf32.f32 "
                        "{%0,%1,%2,%3}, {%4,%5,%6,%7}, {%8,%9}, {%0,%1,%2,%3};"
                        : "+f"(acc[mt][nt][0]), "+f"(acc[mt][nt][1]),
                          "+f"(acc[mt][nt][2]), "+f"(acc[mt][nt][3])
                        : "r"(a[mt][0]), "r"(a[mt][1]), "r"(a[mt][2]), "r"(a[mt][3]),
                          "r"(b[nt][0]), "r"(b[nt][1]));
        }
        __syncthreads();
    }

    // epilogue: c0:(r, 2t) c1:(r, 2t+1) c2:(r+8, 2t) c3:(r+8, 2t+1)
    #pragma unroll
    for (int mt = 0; mt < 4; mt++) {
        int r = row0 + warpM + mt * 16 + g;
        #pragma unroll
        for (int nt = 0; nt < 2; nt++) {
            int c = col0 + warpN + nt * 8 + 2 * t;
            float bx = bias[c], by = bias[c + 1];
            float v0 = acc[mt][nt][0] + bx;
            float v1 = acc[mt][nt][1] + by;
            float v2 = acc[mt][nt][2] + bx;
            float v3 = acc[mt][nt][3] + by;
            if (SEL == 0) {
                v0 = fmaxf(v0, 0.f); v1 = fmaxf(v1, 0.f);
                v2 = fmaxf(v2, 0.f); v3 = fmaxf(v3, 0.f);
            }
            if (r < M)
                *reinterpret_cast<float2*>(C + (size_t)r * Ncols + c) = make_float2(v0, v1);
            if (r + 8 < M)
                *reinterpret_cast<float2*>(C + (size_t)(r + 8) * Ncols + c) = make_float2(v2, v3);
        }
    }
}

// ---------------- CSR construction -------------------------------------------
__global__ void k_zero_cnt(int n) {
    int i = blockIdx.x * blockDim.x + threadIdx.x;
    if (i < n) g_cnt[i] = 0;
}
__global__ void k_count(const void* __restrict__ ei, int E, int N) {
    int e = blockIdx.x * blockDim.x + threadIdx.x;
    if (e < E) atomicAdd(&g_cnt[edge_at(ei, (size_t)E + e, N)], 1);
}
__global__ void k_dis(int n) {
    int i = blockIdx.x * blockDim.x + threadIdx.x;
    if (i < n) g_dis[i] = rsqrtf((float)(g_cnt[i] + 1));
}
__global__ void k_scan1(int N) {
    __shared__ int sh[1024];
    int i = blockIdx.x * 1024 + threadIdx.x;
    int v = (i < N) ? g_cnt[i] : 0;
    sh[threadIdx.x] = v;
    __syncthreads();
    #pragma unroll
    for (int off = 1; off < 1024; off <<= 1) {
        int t = 0;
        if ((int)threadIdx.x >= off) t = sh[threadIdx.x - off];
        __syncthreads();
        sh[threadIdx.x] += t;
        __syncthreads();
    }
    if (i < N) g_incl[i] = sh[threadIdx.x];
    if (threadIdx.x == 1023) g_bsum[blockIdx.x] = sh[1023];
}
__global__ void k_scan2(int nb) {
    if (threadIdx.x == 0 && blockIdx.x == 0) {
        int acc = 0;
        for (int b = 0; b < nb; b++) { int v = g_bsum[b]; g_bsum[b] = acc; acc += v; }
    }
}
__global__ void k_scan3(int N) {
    int i = blockIdx.x * 1024 + threadIdx.x;
    if (i < N) {
        int inc = g_incl[i] + g_bsum[i / 1024];
        g_rowptr[i + 1] = inc;
        g_cursor[i] = inc - g_cnt[i];
    }
    if (i == 0) g_rowptr[0] = 0;
}
__global__ void k_fillcsr(const void* __restrict__ ei, int E, int N) {
    int e = blockIdx.x * blockDim.x + threadIdx.x;
    if (e >= E) return;
    int s = edge_at(ei, (size_t)e, N);
    int d = edge_at(ei, (size_t)E + e, N);
    int p = atomicAdd(&g_cursor[d], 1);
    if (p >= 0 && p < EMAX) {
        g_col[p] = s;
        g_w[p] = g_dis[s] * g_dis[d];
    }
}

// ---------------- propagation ------------------------------------------------
__global__ void k_init(float* __restrict__ out, const float* __restrict__ temp,
                       int n16) {
    int i = blockIdx.x * blockDim.x + threadIdx.x;
    if (i >= n16) return;
    float t0 = temp[0];
    float4 v = reinterpret_cast<const float4*>(g_h)[i];
    reinterpret_cast<float4*>(out)[i] =
        make_float4(t0 * v.x, t0 * v.y, t0 * v.z, t0 * v.w);
}

__global__ void k_prop(int curi, int nxti, float* __restrict__ out,
                       const float* __restrict__ temp, int k, int N) {
    int t = blockIdx.x * blockDim.x + threadIdx.x;
    int row = t >> 4;
    if (row >= N) return;
    int f = (t & 15) << 2;

    const float* cur = bufsel(curi);
    float* nxt = bufsel(nxti);

    float d = g_dis[row];
    float d2 = d * d;
    float4 a = *reinterpret_cast<const float4*>(cur + (size_t)row * 64 + f);
    float ax = d2 * a.x, ay = d2 * a.y, az = d2 * a.z, aw = d2 * a.w;

    int beg = g_rowptr[row];
    int end = g_rowptr[row + 1];
    #pragma unroll 4
    for (int n = beg; n < end; n++) {
        int s = __ldg(&g_col[n]);
        float w = __ldg(&g_w[n]);
        float4 v = *reinterpret_cast<const float4*>(cur + (size_t)s * 64 + f);
        ax = fmaf(w, v.x, ax);
        ay = fmaf(w, v.y, ay);
        az = fmaf(w, v.z, az);
        aw = fmaf(w, v.w, aw);
    }

    size_t oi = (size_t)row * 64 + f;
    *reinterpret_cast<float4*>(nxt + oi) = make_float4(ax, ay, az, aw);

    float tk = temp[k];
    float4 o = *reinterpret_cast<const float4*>(out + oi);
    o.x = fmaf(tk, ax, o.x);
    o.y = fmaf(tk, ay, o.y);
    o.z = fmaf(tk, az, o.z);
    o.w = fmaf(tk, aw, o.w);
    *reinterpret_cast<float4*>(out + oi) = o;
}

// ---------------- launch ------------------------------------------------------
extern "C" void kernel_launch(void* const* d_in, const int* in_sizes, int n_in,
                              void* d_out, int out_size) {
    const float* x    = (const float*)d_in[0];
    const void*  ei   = (const void*)d_in[1];
    const float* W1   = (const float*)d_in[2];
    const float* b1   = (const float*)d_in[3];
    const float* W2   = (const float*)d_in[4];
    const float* b2   = (const float*)d_in[5];
    const float* temp = (const float*)d_in[6];
    float* out = (float*)d_out;

    const int HID = in_sizes[3];                 // 256
    const int OUT = in_sizes[5];                 // 64
    const int INF = in_sizes[2] / HID;           // 512
    const int N   = in_sizes[0] / INF;           // 100000
    const int E   = in_sizes[1] / 2;             // 3200000

    // launch order keeps GEMM1 at ncu slot 6 (-s 5 -c 1)
    k_detect  <<<1, 256>>>(ei, E, N);                               // 1
    k_zero_cnt<<<(N + 255) / 256, 256>>>(N);                        // 2
    k_count   <<<(E + 255) / 256, 256>>>(ei, E, N);                 // 3
    { dim3 g(HID / 32, INF / 32); dim3 b(32, 8);
      k_transpose<<<g, b>>>(W1, g_W1t, INF, HID); }                 // 4
    { dim3 g(OUT / 32, HID / 32); dim3 b(32, 8);
      k_transpose<<<g, b>>>(W2, g_W2t, HID, OUT); }                 // 5

    const int mrows = (N + 127) / 128;
    { dim3 g(HID / 64, mrows);
      mma_gemm<512, 0><<<g, 256>>>(x, g_W1t, b1, N, HID); }         // 6
    { dim3 g(OUT / 64, mrows);
      mma_gemm<256, 1><<<g, 256>>>(nullptr, g_W2t, b2, N, OUT); }   // 7

    k_dis    <<<(N + 255) / 256, 256>>>(N);
    const int nblk = (N + 1023) / 1024;
    k_scan1  <<<nblk, 1024>>>(N);
    k_scan2  <<<1, 32>>>(nblk);
    k_scan3  <<<nblk, 1024>>>(N);
    k_fillcsr<<<(E + 255) / 256, 256>>>(ei, E, N);

    const int n16 = N * 16;
    k_init<<<(n16 + 255) / 256, 256>>>(out, temp, n16);

    int cur = 0, nxt = 1;
    for (int k = 1; k <= 10; k++) {
        k_prop<<<(n16 + 255) / 256, 256>>>(cur, nxt, out, temp, k, N);
        int t = cur;
        cur = nxt;
        nxt = (t == 0) ? 2 : t;
    }
}

// round 8
// speedup vs baseline: 1.4705x; 1.4705x over previous
#include <cuda_runtime.h>
#include <cstdint>
#include <cstddef>

#define NMAX 100000
#define EMAX 3200000
#define NBLK_SCAN ((NMAX + 1023) / 1024)

// ---------------- static device scratch (no allocation anywhere) -------------
__device__ __align__(128) float g_h1[(size_t)NMAX * 256];   // relu(x@W1+b1)
__device__ __align__(128) float g_h [(size_t)NMAX * 64];    // MLP output
__device__ __align__(128) float g_bufA[(size_t)NMAX * 64];
__device__ __align__(128) float g_bufB[(size_t)NMAX * 64];
__device__ __align__(128) float g_dis[NMAX];
__device__ __align__(128) int   g_cnt[NMAX];
__device__ __align__(128) int   g_incl[NMAX];
__device__ __align__(128) int   g_bsum[NBLK_SCAN + 1];
__device__ __align__(128) int   g_rowptr[NMAX + 1];
__device__ __align__(128) int   g_cursor[NMAX];
__device__ __align__(128) int   g_col[EMAX];
__device__ __align__(128) float g_w[EMAX];
__device__ int g_is64;

__device__ __forceinline__ float* bufsel(int i) {
    return i == 0 ? g_h : (i == 1 ? g_bufA : g_bufB);
}

// ---------------- dtype detection --------------------------------------------
__global__ void k_detect(const void* ei, int E, int N) {
    __shared__ int bad;
    if (threadIdx.x == 0) bad = 0;
    __syncthreads();
    const long long* p = (const long long*)ei;
    int lim = (E < 4096) ? E : 4096;
    for (int i = threadIdx.x; i < lim; i += blockDim.x) {
        long long v = p[i];
        if (v < 0 || v >= (long long)N) bad = 1;
    }
    __syncthreads();
    if (threadIdx.x == 0) g_is64 = bad ? 0 : 1;
}

__device__ __forceinline__ int edge_at(const void* ei, size_t j, int N) {
    long long v;
    if (g_is64) v = ((const long long*)ei)[j];
    else        v = (long long)((const int*)ei)[j];
    if (v < 0) v = 0;
    if (v >= N) v = N - 1;
    return (int)v;
}

// ---------------- tf32 mma.sync GEMM -----------------------------------------
// C[M x Ncols] = A[M x KTOT] @ B[KTOT x Ncols]  (+bias, optional relu)
// B consumed in native row-major [K][N] layout — no pre-transpose.
// Block 128x64, BK=32, 8 warps as 2(M) x 4(N); warp tile 64x16 = 4x2 m16n8k8.
__device__ __forceinline__ uint32_t f2tf(float f) {
    uint32_t r;
    asm("cvt.rna.tf32.f32 %0, %1;" : "=r"(r) : "f"(f));
    return r;
}

template<int KTOT, int SEL>
__global__ void __launch_bounds__(256) mma_gemm(const float* __restrict__ Ain,
                                                const float* __restrict__ B,
                                                const float* __restrict__ bias,
                                                int M, int Ncols) {
    constexpr int SA = 36;                  // A smem row stride (words)
    constexpr int SB = 72;                  // B smem row stride (words): 72%32=8
    __shared__ uint32_t As[128 * SA];       // [m][k]
    __shared__ uint32_t Bs[32 * SB];        // [k][n]

    const float* A = (SEL == 0) ? Ain : (const float*)g_h1;
    float* C       = (SEL == 0) ? g_h1 : g_h;

    const int tid = threadIdx.x;
    const int wid = tid >> 5;
    const int lane = tid & 31;
    const int g = lane >> 2;                // group id 0..7
    const int t = lane & 3;                 // thread-in-group 0..3
    const int row0 = blockIdx.y * 128;
    const int col0 = blockIdx.x * 64;
    const int warpM = (wid & 1) * 64;
    const int warpN = (wid >> 1) * 16;

    float acc[4][2][4];
    #pragma unroll
    for (int mt = 0; mt < 4; mt++)
        #pragma unroll
        for (int nt = 0; nt < 2; nt++)
            #pragma unroll
            for (int r = 0; r < 4; r++) acc[mt][nt][r] = 0.f;

    for (int kt = 0; kt < KTOT / 32; kt++) {
        // A tile: 128 rows x 32 k -> 1024 float4, 4 per thread (coalesced)
        #pragma unroll
        for (int i = 0; i < 4; i++) {
            int idx = tid + i * 256;
            int m = idx >> 3, k4 = idx & 7;
            int gr = row0 + m;
            float4 v = make_float4(0.f, 0.f, 0.f, 0.f);
            if (gr < M)
                v = *reinterpret_cast<const float4*>(A + (size_t)gr * KTOT + kt * 32 + k4 * 4);
            uint4 w4 = make_uint4(f2tf(v.x), f2tf(v.y), f2tf(v.z), f2tf(v.w));
            *reinterpret_cast<uint4*>(&As[m * SA + k4 * 4]) = w4;
        }
        // B tile: 32 k x 64 n, native row-major -> 512 float4, 2 per thread
        #pragma unroll
        for (int i = 0; i < 2; i++) {
            int idx = tid + i * 256;
            int k = idx >> 4, n4 = idx & 15;
            float4 v = *reinterpret_cast<const float4*>(B + (size_t)(kt * 32 + k) * Ncols + col0 + n4 * 4);
            uint4 w4 = make_uint4(f2tf(v.x), f2tf(v.y), f2tf(v.z), f2tf(v.w));
            *reinterpret_cast<uint4*>(&Bs[k * SB + n4 * 4]) = w4;
        }
        __syncthreads();

        #pragma unroll
        for (int kk = 0; kk < 32; kk += 8) {
            uint32_t a[4][4], b[2][2];
            #pragma unroll
            for (int mt = 0; mt < 4; mt++) {
                int mr = warpM + mt * 16 + g;
                a[mt][0] = As[mr * SA + kk + t];
                a[mt][1] = As[(mr + 8) * SA + kk + t];
                a[mt][2] = As[mr * SA + kk + t + 4];
                a[mt][3] = As[(mr + 8) * SA + kk + t + 4];
            }
            #pragma unroll
            for (int nt = 0; nt < 2; nt++) {
                int nc = warpN + nt * 8 + g;
                b[nt][0] = Bs[(kk + t) * SB + nc];        // B[k][n], k=t
                b[nt][1] = Bs[(kk + t + 4) * SB + nc];    // k=t+4
            }
            #pragma unroll
            for (int mt = 0; mt < 4; mt++)
                #pragma unroll
                for (int nt = 0; nt < 2; nt++)
                    asm volatile(
                        "mma.sync.aligned.m16n8k8.row.col.f32.tf32.tf32.f32 "
                        "{%0,%1,%2,%3}, {%4,%5,%6,%7}, {%8,%9}, {%0,%1,%2,%3};"
                        : "+f"(acc[mt][nt][0]), "+f"(acc[mt][nt][1]),
                          "+f"(acc[mt][nt][2]), "+f"(acc[mt][nt][3])
                        : "r"(a[mt][0]), "r"(a[mt][1]), "r"(a[mt][2]), "r"(a[mt][3]),
                          "r"(b[nt][0]), "r"(b[nt][1]));
        }
        __syncthreads();
    }

    // epilogue: c0:(r, 2t) c1:(r, 2t+1) c2:(r+8, 2t) c3:(r+8, 2t+1)
    #pragma unroll
    for (int mt = 0; mt < 4; mt++) {
        int r = row0 + warpM + mt * 16 + g;
        #pragma unroll
        for (int nt = 0; nt < 2; nt++) {
            int c = col0 + warpN + nt * 8 + 2 * t;
            float bx = bias[c], by = bias[c + 1];
            float v0 = acc[mt][nt][0] + bx;
            float v1 = acc[mt][nt][1] + by;
            float v2 = acc[mt][nt][2] + bx;
            float v3 = acc[mt][nt][3] + by;
            if (SEL == 0) {
                v0 = fmaxf(v0, 0.f); v1 = fmaxf(v1, 0.f);
                v2 = fmaxf(v2, 0.f); v3 = fmaxf(v3, 0.f);
            }
            if (r < M)
                *reinterpret_cast<float2*>(C + (size_t)r * Ncols + c) = make_float2(v0, v1);
            if (r + 8 < M)
                *reinterpret_cast<float2*>(C + (size_t)(r + 8) * Ncols + c) = make_float2(v2, v3);
        }
    }
}

// ---------------- CSR construction -------------------------------------------
__global__ void k_zero_cnt(int n) {
    int i = blockIdx.x * blockDim.x + threadIdx.x;
    if (i < n) g_cnt[i] = 0;
}
__global__ void k_count(const void* __restrict__ ei, int E, int N) {
    int e = blockIdx.x * blockDim.x + threadIdx.x;
    if (e < E) atomicAdd(&g_cnt[edge_at(ei, (size_t)E + e, N)], 1);
}
__global__ void k_dis(int n) {
    int i = blockIdx.x * blockDim.x + threadIdx.x;
    if (i < n) g_dis[i] = rsqrtf((float)(g_cnt[i] + 1));
}
__global__ void k_scan1(int N) {
    __shared__ int sh[1024];
    int i = blockIdx.x * 1024 + threadIdx.x;
    int v = (i < N) ? g_cnt[i] : 0;
    sh[threadIdx.x] = v;
    __syncthreads();
    #pragma unroll
    for (int off = 1; off < 1024; off <<= 1) {
        int t = 0;
        if ((int)threadIdx.x >= off) t = sh[threadIdx.x - off];
        __syncthreads();
        sh[threadIdx.x] += t;
        __syncthreads();
    }
    if (i < N) g_incl[i] = sh[threadIdx.x];
    if (threadIdx.x == 1023) g_bsum[blockIdx.x] = sh[1023];
}
__global__ void k_scan2(int nb) {
    if (threadIdx.x == 0 && blockIdx.x == 0) {
        int acc = 0;
        for (int b = 0; b < nb; b++) { int v = g_bsum[b]; g_bsum[b] = acc; acc += v; }
    }
}
__global__ void k_scan3(int N) {
    int i = blockIdx.x * 1024 + threadIdx.x;
    if (i < N) {
        int inc = g_incl[i] + g_bsum[i / 1024];
        g_rowptr[i + 1] = inc;
        g_cursor[i] = inc - g_cnt[i];
    }
    if (i == 0) g_rowptr[0] = 0;
}
__global__ void k_fillcsr(const void* __restrict__ ei, int E, int N) {
    int e = blockIdx.x * blockDim.x + threadIdx.x;
    if (e >= E) return;
    int s = edge_at(ei, (size_t)e, N);
    int d = edge_at(ei, (size_t)E + e, N);
    int p = atomicAdd(&g_cursor[d], 1);
    if (p >= 0 && p < EMAX) {
        g_col[p] = s;
        g_w[p] = g_dis[s] * g_dis[d];
    }
}

// ---------------- propagation ------------------------------------------------
__global__ void k_init(float* __restrict__ out, const float* __restrict__ temp,
                       int n16) {
    int i = blockIdx.x * blockDim.x + threadIdx.x;
    if (i >= n16) return;
    float t0 = temp[0];
    float4 v = reinterpret_cast<const float4*>(g_h)[i];
    reinterpret_cast<float4*>(out)[i] =
        make_float4(t0 * v.x, t0 * v.y, t0 * v.z, t0 * v.w);
}

__global__ void k_prop(int curi, int nxti, float* __restrict__ out,
                       const float* __restrict__ temp, int k, int N) {
    int t = blockIdx.x * blockDim.x + threadIdx.x;
    int row = t >> 4;
    if (row >= N) return;
    int f = (t & 15) << 2;

    const float* cur = bufsel(curi);
    float* nxt = bufsel(nxti);

    float d = g_dis[row];
    float d2 = d * d;
    float4 a = *reinterpret_cast<const float4*>(cur + (size_t)row * 64 + f);
    float ax = d2 * a.x, ay = d2 * a.y, az = d2 * a.z, aw = d2 * a.w;

    int beg = g_rowptr[row];
    int end = g_rowptr[row + 1];
    #pragma unroll 4
    for (int n = beg; n < end; n++) {
        int s = __ldg(&g_col[n]);
        float w = __ldg(&g_w[n]);
        float4 v = *reinterpret_cast<const float4*>(cur + (size_t)s * 64 + f);
        ax = fmaf(w, v.x, ax);
        ay = fmaf(w, v.y, ay);
        az = fmaf(w, v.z, az);
        aw = fmaf(w, v.w, aw);
    }

    size_t oi = (size_t)row * 64 + f;
    *reinterpret_cast<float4*>(nxt + oi) = make_float4(ax, ay, az, aw);

    float tk = temp[k];
    float4 o = *reinterpret_cast<const float4*>(out + oi);
    o.x = fmaf(tk, ax, o.x);
    o.y = fmaf(tk, ay, o.y);
    o.z = fmaf(tk, az, o.z);
    o.w = fmaf(tk, aw, o.w);
    *reinterpret_cast<float4*>(out + oi) = o;
}

// ---------------- launch ------------------------------------------------------
extern "C" void kernel_launch(void* const* d_in, const int* in_sizes, int n_in,
                              void* d_out, int out_size) {
    const float* x    = (const float*)d_in[0];
    const void*  ei   = (const void*)d_in[1];
    const float* W1   = (const float*)d_in[2];
    const float* b1   = (const float*)d_in[3];
    const float* W2   = (const float*)d_in[4];
    const float* b2   = (const float*)d_in[5];
    const float* temp = (const float*)d_in[6];
    float* out = (float*)d_out;

    const int HID = in_sizes[3];                 // 256
    const int OUT = in_sizes[5];                 // 64
    const int INF = in_sizes[2] / HID;           // 512
    const int N   = in_sizes[0] / INF;           // 100000
    const int E   = in_sizes[1] / 2;             // 3200000

    k_detect  <<<1, 256>>>(ei, E, N);                               // 1
    k_zero_cnt<<<(N + 255) / 256, 256>>>(N);                        // 2
    k_count   <<<(E + 255) / 256, 256>>>(ei, E, N);                 // 3

    const int mrows = (N + 127) / 128;
    { dim3 g(HID / 64, mrows);
      mma_gemm<512, 0><<<g, 256>>>(x, W1, b1, N, HID); }            // 4
    { dim3 g(OUT / 64, mrows);
      mma_gemm<256, 1><<<g, 256>>>(nullptr, W2, b2, N, OUT); }      // 5

    k_dis    <<<(N + 255) / 256, 256>>>(N);                         // 6
    const int nblk = (N + 1023) / 1024;
    k_scan1  <<<nblk, 1024>>>(N);
    k_scan2  <<<1, 32>>>(nblk);
    k_scan3  <<<nblk, 1024>>>(N);
    k_fillcsr<<<(E + 255) / 256, 256>>>(ei, E, N);

    const int n16 = N * 16;
    k_init<<<(n16 + 255) / 256, 256>>>(out, temp, n16);

    int cur = 0, nxt = 1;
    for (int k = 1; k <= 10; k++) {
        k_prop<<<(n16 + 255) / 256, 256>>>(cur, nxt, out, temp, k, N);
        int t = cur;
        cur = nxt;
        nxt = (t == 0) ? 2 : t;
    }
}

// round 15
// speedup vs baseline: 1.8324x; 1.2461x over previous
#include <cuda_runtime.h>
#include <cuda_bf16.h>
#include <cstdint>
#include <cstddef>

#define NMAX 100000
#define EMAX 3200000
#define NBLK_SCAN ((NMAX + 1023) / 1024)

// ---------------- static device scratch (no allocation anywhere) -------------
__device__ __align__(128) float g_h1[(size_t)NMAX * 256];   // relu(x@W1+b1)
__device__ __align__(128) float g_h [(size_t)NMAX * 64];    // MLP output (fp32)
__device__ __align__(128) __nv_bfloat162 g_hb0[(size_t)NMAX * 32]; // prop state A
__device__ __align__(128) __nv_bfloat162 g_hb1[(size_t)NMAX * 32]; // prop state B
__device__ __align__(128) float g_dis[NMAX];
__device__ __align__(128) int   g_cnt[NMAX];
__device__ __align__(128) int   g_incl[NMAX];
__device__ __align__(128) int   g_bsum[NBLK_SCAN + 1];
__device__ __align__(128) int   g_rowptr[NMAX + 1];
__device__ __align__(128) int   g_cursor[NMAX];
__device__ __align__(128) int   g_col[EMAX];
__device__ __align__(128) float g_w[EMAX];
__device__ int g_is64;

// ---------------- dtype detection --------------------------------------------
__global__ void k_detect(const void* ei, int E, int N) {
    __shared__ int bad;
    if (threadIdx.x == 0) bad = 0;
    __syncthreads();
    const long long* p = (const long long*)ei;
    int lim = (E < 4096) ? E : 4096;
    for (int i = threadIdx.x; i < lim; i += blockDim.x) {
        long long v = p[i];
        if (v < 0 || v >= (long long)N) bad = 1;
    }
    __syncthreads();
    if (threadIdx.x == 0) g_is64 = bad ? 0 : 1;
}

__device__ __forceinline__ int edge_at(const void* ei, size_t j, int N) {
    long long v;
    if (g_is64) v = ((const long long*)ei)[j];
    else        v = (long long)((const int*)ei)[j];
    if (v < 0) v = 0;
    if (v >= N) v = N - 1;
    return (int)v;
}

// ---------------- SGEMM (proven R2 kernel): C = op(A@B + bias) ---------------
// SEL==0 : A = param (x),  C = g_h1, ReLU      SEL==1 : A = g_h1, C = g_h
template<int BM, int BN, int BK, int TM, int TN, int SEL>
__global__ void sgemm_kernel(const float* __restrict__ A_in,
                             const float* __restrict__ B,
                             const float* __restrict__ bias,
                             int M, int N, int K) {
    constexpr int NT = (BM / TM) * (BN / TN);
    constexpr bool RELU = (SEL == 0);
    const float* A = (SEL == 0) ? A_in : (const float*)g_h1;
    float* C       = (SEL == 0) ? g_h1 : g_h;

    __shared__ float As[BK][BM];
    __shared__ float Bs[BK][BN];

    const int tid  = threadIdx.x;
    const int row0 = blockIdx.y * BM;
    const int col0 = blockIdx.x * BN;

    const int tcols = BN / TN;
    const int tr = tid / tcols;
    const int tc = tid % tcols;

    float acc[TM][TN];
    #pragma unroll
    for (int i = 0; i < TM; i++)
        #pragma unroll
        for (int j = 0; j < TN; j++) acc[i][j] = 0.0f;

    constexpr int A_LD = (BM * BK) / (NT * 4);
    constexpr int B_LD = (BK * BN) / (NT * 4);

    for (int kt = 0; kt < K; kt += BK) {
        #pragma unroll
        for (int i = 0; i < A_LD; i++) {
            int idx = tid + i * NT;
            int a_r = idx / (BK / 4);
            int a_c = (idx % (BK / 4)) * 4;
            float4 v = make_float4(0.f, 0.f, 0.f, 0.f);
            int gr = row0 + a_r;
            if (gr < M)
                v = *reinterpret_cast<const float4*>(A + (size_t)gr * K + kt + a_c);
            As[a_c + 0][a_r] = v.x;
            As[a_c + 1][a_r] = v.y;
            As[a_c + 2][a_r] = v.z;
            As[a_c + 3][a_r] = v.w;
        }
        #pragma unroll
        for (int i = 0; i < B_LD; i++) {
            int idx = tid + i * NT;
            int b_r = idx / (BN / 4);
            int b_c = (idx % (BN / 4)) * 4;
            float4 v = *reinterpret_cast<const float4*>(B + (size_t)(kt + b_r) * N + col0 + b_c);
            *reinterpret_cast<float4*>(&Bs[b_r][b_c]) = v;
        }
        __syncthreads();

        #pragma unroll
        for (int kk = 0; kk < BK; kk++) {
            float ar[TM], br[TN];
            #pragma unroll
            for (int i = 0; i < TM; i++) ar[i] = As[kk][tr * TM + i];
            #pragma unroll
            for (int j = 0; j < TN; j++) br[j] = Bs[kk][tc * TN + j];
            #pragma unroll
            for (int i = 0; i < TM; i++)
                #pragma unroll
                for (int j = 0; j < TN; j++)
                    acc[i][j] = fmaf(ar[i], br[j], acc[i][j]);
        }
        __syncthreads();
    }

    #pragma unroll
    for (int i = 0; i < TM; i++) {
        int gr = row0 + tr * TM + i;
        if (gr >= M) continue;
        #pragma unroll
        for (int j = 0; j < TN; j += 4) {
            int gc = col0 + tc * TN + j;
            float4 b4 = *reinterpret_cast<const float4*>(bias + gc);
            float4 v;
            v.x = acc[i][j + 0] + b4.x;
            v.y = acc[i][j + 1] + b4.y;
            v.z = acc[i][j + 2] + b4.z;
            v.w = acc[i][j + 3] + b4.w;
            if (RELU) {
                v.x = fmaxf(v.x, 0.f); v.y = fmaxf(v.y, 0.f);
                v.z = fmaxf(v.z, 0.f); v.w = fmaxf(v.w, 0.f);
            }
            *reinterpret_cast<float4*>(C + (size_t)gr * N + gc) = v;
        }
    }
}

// ---------------- CSR construction -------------------------------------------
__global__ void k_zero_cnt(int n) {
    int i = blockIdx.x * blockDim.x + threadIdx.x;
    if (i < n) g_cnt[i] = 0;
}
__global__ void k_count(const void* __restrict__ ei, int E, int N) {
    int e = blockIdx.x * blockDim.x + threadIdx.x;
    if (e < E) atomicAdd(&g_cnt[edge_at(ei, (size_t)E + e, N)], 1);
}
__global__ void k_dis(int n) {
    int i = blockIdx.x * blockDim.x + threadIdx.x;
    if (i < n) g_dis[i] = rsqrtf((float)(g_cnt[i] + 1));
}
__global__ void k_scan1(int N) {
    __shared__ int sh[1024];
    int i = blockIdx.x * 1024 + threadIdx.x;
    int v = (i < N) ? g_cnt[i] : 0;
    sh[threadIdx.x] = v;
    __syncthreads();
    #pragma unroll
    for (int off = 1; off < 1024; off <<= 1) {
        int t = 0;
        if ((int)threadIdx.x >= off) t = sh[threadIdx.x - off];
        __syncthreads();
        sh[threadIdx.x] += t;
        __syncthreads();
    }
    if (i < N) g_incl[i] = sh[threadIdx.x];
    if (threadIdx.x == 1023) g_bsum[blockIdx.x] = sh[1023];
}
__global__ void k_scan2(int nb) {
    if (threadIdx.x == 0 && blockIdx.x == 0) {
        int acc = 0;
        for (int b = 0; b < nb; b++) { int v = g_bsum[b]; g_bsum[b] = acc; acc += v; }
    }
}
__global__ void k_scan3(int N) {
    int i = blockIdx.x * 1024 + threadIdx.x;
    if (i < N) {
        int inc = g_incl[i] + g_bsum[i / 1024];
        g_rowptr[i + 1] = inc;
        g_cursor[i] = inc - g_cnt[i];
    }
    if (i == 0) g_rowptr[0] = 0;
}
__global__ void k_fillcsr(const void* __restrict__ ei, int E, int N) {
    int e = blockIdx.x * blockDim.x + threadIdx.x;
    if (e >= E) return;
    int s = edge_at(ei, (size_t)e, N);
    int d = edge_at(ei, (size_t)E + e, N);
    int p = atomicAdd(&g_cursor[d], 1);
    if (p >= 0 && p < EMAX) {
        g_col[p] = s;
        g_w[p] = g_dis[s] * g_dis[d];
    }
}

// ---------------- propagation (bf16 state, fp32 accumulate) ------------------
// out = temp[0]*h ; hb0 = bf16(h)
__global__ void k_init(float* __restrict__ out, const float* __restrict__ temp,
                       int n16) {
    int i = blockIdx.x * blockDim.x + threadIdx.x;
    if (i >= n16) return;
    float t0 = temp[0];
    float4 v = reinterpret_cast<const float4*>(g_h)[i];
    reinterpret_cast<float4*>(out)[i] =
        make_float4(t0 * v.x, t0 * v.y, t0 * v.z, t0 * v.w);
    int node = i >> 4, f = i & 15;
    size_t b = (size_t)node * 32 + (size_t)f * 2;
    g_hb0[b]     = __floats2bfloat162_rn(v.x, v.y);
    g_hb0[b + 1] = __floats2bfloat162_rn(v.z, v.w);
}

__device__ __forceinline__ float2 bf2f(uint32_t u) {
    return __bfloat1622float2(*reinterpret_cast<const __nv_bfloat162*>(&u));
}

// nxt[row] = dis^2*cur[row] + sum_n w[n]*cur[col[n]]   (bf16 gather, fp32 acc)
// out[row] += temp[k]*accum (exact fp32 accumulator, pre-rounding)
// 8 threads per row; each handles 8 features (one uint4 = 4 x bf162).
__global__ void k_prop(int curi, float* __restrict__ out,
                       const float* __restrict__ temp, int k, int N) {
    int t = blockIdx.x * blockDim.x + threadIdx.x;
    int row = t >> 3;
    if (row >= N) return;
    int f = t & 7;

    const __nv_bfloat162* cur = curi ? g_hb1 : g_hb0;
    __nv_bfloat162*       nxt = curi ? g_hb0 : g_hb1;

    float d = g_dis[row];
    float d2 = d * d;
    size_t base = (size_t)row * 32 + (size_t)f * 4;   // 4 bf162 per thread

    float acc[8];
    {
        uint4 u = *reinterpret_cast<const uint4*>(cur + base);
        float2 p0 = bf2f(u.x), p1 = bf2f(u.y), p2 = bf2f(u.z), p3 = bf2f(u.w);
        acc[0] = d2 * p0.x; acc[1] = d2 * p0.y;
        acc[2] = d2 * p1.x; acc[3] = d2 * p1.y;
        acc[4] = d2 * p2.x; acc[5] = d2 * p2.y;
        acc[6] = d2 * p3.x; acc[7] = d2 * p3.y;
    }

    int beg = g_rowptr[row];
    int end = g_rowptr[row + 1];
    #pragma unroll 4
    for (int n = beg; n < end; n++) {
        int s = __ldg(&g_col[n]);
        float w = __ldg(&g_w[n]);
        uint4 u = *reinterpret_cast<const uint4*>(cur + (size_t)s * 32 + (size_t)f * 4);
        float2 p0 = bf2f(u.x), p1 = bf2f(u.y), p2 = bf2f(u.z), p3 = bf2f(u.w);
        acc[0] = fmaf(w, p0.x, acc[0]); acc[1] = fmaf(w, p0.y, acc[1]);
        acc[2] = fmaf(w, p1.x, acc[2]); acc[3] = fmaf(w, p1.y, acc[3]);
        acc[4] = fmaf(w, p2.x, acc[4]); acc[5] = fmaf(w, p2.y, acc[5]);
        acc[6] = fmaf(w, p3.x, acc[6]); acc[7] = fmaf(w, p3.y, acc[7]);
    }

    {   // store bf16 state
        __nv_bfloat162 o0 = __floats2bfloat162_rn(acc[0], acc[1]);
        __nv_bfloat162 o1 = __floats2bfloat162_rn(acc[2], acc[3]);
        __nv_bfloat162 o2 = __floats2bfloat162_rn(acc[4], acc[5]);
        __nv_bfloat162 o3 = __floats2bfloat162_rn(acc[6], acc[7]);
        uint4 pk;
        pk.x = *reinterpret_cast<uint32_t*>(&o0);
        pk.y = *reinterpret_cast<uint32_t*>(&o1);
        pk.z = *reinterpret_cast<uint32_t*>(&o2);
        pk.w = *reinterpret_cast<uint32_t*>(&o3);
        *reinterpret_cast<uint4*>(nxt + base) = pk;
    }

    float tk = temp[k];
    size_t oi = (size_t)row * 64 + (size_t)f * 8;
    float4 o0 = *reinterpret_cast<const float4*>(out + oi);
    float4 o1 = *reinterpret_cast<const float4*>(out + oi + 4);
    o0.x = fmaf(tk, acc[0], o0.x); o0.y = fmaf(tk, acc[1], o0.y);
    o0.z = fmaf(tk, acc[2], o0.z); o0.w = fmaf(tk, acc[3], o0.w);
    o1.x = fmaf(tk, acc[4], o1.x); o1.y = fmaf(tk, acc[5], o1.y);
    o1.z = fmaf(tk, acc[6], o1.z); o1.w = fmaf(tk, acc[7], o1.w);
    *reinterpret_cast<float4*>(out + oi)     = o0;
    *reinterpret_cast<float4*>(out + oi + 4) = o1;
}

// ---------------- launch ------------------------------------------------------
extern "C" void kernel_launch(void* const* d_in, const int* in_sizes, int n_in,
                              void* d_out, int out_size) {
    const float* x    = (const float*)d_in[0];
    const void*  ei   = (const void*)d_in[1];
    const float* W1   = (const float*)d_in[2];
    const float* b1   = (const float*)d_in[3];
    const float* W2   = (const float*)d_in[4];
    const float* b2   = (const float*)d_in[5];
    const float* temp = (const float*)d_in[6];
    float* out = (float*)d_out;

    const int HID = in_sizes[3];                 // 256
    const int OUT = in_sizes[5];                 // 64
    const int INF = in_sizes[2] / HID;           // 512
    const int N   = in_sizes[0] / INF;           // 100000
    const int E   = in_sizes[1] / 2;             // 3200000

    k_detect  <<<1, 256>>>(ei, E, N);                               // 1
    k_zero_cnt<<<(N + 255) / 256, 256>>>(N);                        // 2
    k_count   <<<(E + 255) / 256, 256>>>(ei, E, N);                 // 3

    {   // GEMM1: x[N,512] @ W1[512,256] -> g_h1 (relu)
        dim3 g(HID / 128, (N + 127) / 128);
        sgemm_kernel<128, 128, 16, 8, 8, 0><<<g, 256>>>(x, W1, b1, N, HID, INF); // 4
    }
    {   // GEMM2: g_h1[N,256] @ W2[256,64] -> g_h
        dim3 g(OUT / 64, (N + 127) / 128);
        sgemm_kernel<128, 64, 16, 8, 4, 1><<<g, 256>>>(nullptr, W2, b2, N, OUT, HID); // 5
    }

    k_dis    <<<(N + 255) / 256, 256>>>(N);                         // 6
    const int nblk = (N + 1023) / 1024;
    k_scan1  <<<nblk, 1024>>>(N);
    k_scan2  <<<1, 32>>>(nblk);
    k_scan3  <<<nblk, 1024>>>(N);
    k_fillcsr<<<(E + 255) / 256, 256>>>(ei, E, N);

    const int n16 = N * 16;
    k_init<<<(n16 + 255) / 256, 256>>>(out, temp, n16);

    // iter k reads hb[cur], writes hb[1-cur]; cur starts at 0 (k_init wrote hb0)
    const int n8 = N * 8;
    int cur = 0;
    for (int k = 1; k <= 10; k++) {
        k_prop<<<(n8 + 255) / 256, 256>>>(cur, out, temp, k, N);
        cur ^= 1;
    }
}